// round 3
// baseline (speedup 1.0000x reference)
#include <cuda_runtime.h>
#include <cstdint>

#define N_NODES 100000
#define N_EDGES 1250000
#define FEATS   64

// Scratch accumulator for segment_sum result (25.6 MB), float4 for guaranteed
// 16B alignment. Static __device__ array per allocation rules.
__device__ float4 g_ah4[N_NODES * (FEATS / 4)];

// ---------------------------------------------------------------------------
// Kernel 1: zero the accumulator (float4 stores, fully coalesced)
// ---------------------------------------------------------------------------
__global__ void zero_kernel() {
    unsigned i = blockIdx.x * blockDim.x + threadIdx.x;
    const unsigned n4 = N_NODES * (FEATS / 4);
    if (i < n4) {
        g_ah4[i] = make_float4(0.f, 0.f, 0.f, 0.f);
    }
}

// ---------------------------------------------------------------------------
// Kernel 2: edge scatter-add.  16 threads per edge, each handles one float4
// chunk of the 64-float feature row.  h (25.6 MB) is L2-resident, so the
// gather is mostly an L2 hit.  atomicAdd with unused return lowers to
// REDG.ADD.F32 (fire-and-forget scalar reduction).
// NOTE: src/dst are int32 (JAX x64 disabled: jnp.int64 -> int32).
// ---------------------------------------------------------------------------
__global__ __launch_bounds__(256)
void scatter_kernel(const float4* __restrict__ h4,
                    const int* __restrict__ src,
                    const int* __restrict__ dst) {
    unsigned idx = blockIdx.x * blockDim.x + threadIdx.x;   // < E*16 = 20M
    unsigned e = idx >> 4;        // edge id
    unsigned c = idx & 15;        // float4 chunk within feature row
    if (e >= N_EDGES) return;

    unsigned s = (unsigned)src[e];
    unsigned d = (unsigned)dst[e];

    float4 v = __ldg(&h4[s * 16u + c]);
    float* p = reinterpret_cast<float*>(&g_ah4[d * 16u + c]);

    atomicAdd(p + 0, v.x);
    atomicAdd(p + 1, v.y);
    atomicAdd(p + 2, v.z);
    atomicAdd(p + 3, v.w);
}

// ---------------------------------------------------------------------------
// Kernel 3: out = relu(ah @ W^T + b).
// W (64x64 fp32, 16 KB) transposed into smem so the inner o-loop reads
// contiguous float4 (warp-broadcast, conflict-free).  One thread per node:
// 64 accumulators in registers, 4096 FFMA per thread.
// ---------------------------------------------------------------------------
__global__ __launch_bounds__(256)
void gemm_relu_kernel(const float* __restrict__ W,
                      const float* __restrict__ b,
                      float* __restrict__ out) {
    __shared__ float Ws[FEATS * FEATS];   // Ws[k*64 + o] = W[o][k]
    __shared__ float bs[FEATS];

    for (int i = threadIdx.x; i < FEATS * FEATS; i += 256) {
        int o = i >> 6;
        int k = i & 63;
        Ws[k * FEATS + o] = W[i];
    }
    if (threadIdx.x < FEATS) bs[threadIdx.x] = b[threadIdx.x];
    __syncthreads();

    unsigned node = blockIdx.x * 256u + threadIdx.x;
    if (node >= N_NODES) return;

    const float4* arow = &g_ah4[node * 16u];

    float acc[FEATS];
    #pragma unroll
    for (int o = 0; o < FEATS; o++) acc[o] = bs[o];

    #pragma unroll 1
    for (int k4 = 0; k4 < 16; k4++) {
        float4 a = arow[k4];
        float av[4] = {a.x, a.y, a.z, a.w};
        #pragma unroll
        for (int j = 0; j < 4; j++) {
            const float4* wrow =
                reinterpret_cast<const float4*>(Ws + (k4 * 4 + j) * FEATS);
            float aj = av[j];
            #pragma unroll
            for (int o4 = 0; o4 < 16; o4++) {
                float4 w = wrow[o4];
                acc[o4 * 4 + 0] += aj * w.x;
                acc[o4 * 4 + 1] += aj * w.y;
                acc[o4 * 4 + 2] += aj * w.z;
                acc[o4 * 4 + 3] += aj * w.w;
            }
        }
    }

    float4* outp = reinterpret_cast<float4*>(out + node * 64u);
    #pragma unroll
    for (int o4 = 0; o4 < 16; o4++) {
        float4 r;
        r.x = fmaxf(acc[o4 * 4 + 0], 0.f);
        r.y = fmaxf(acc[o4 * 4 + 1], 0.f);
        r.z = fmaxf(acc[o4 * 4 + 2], 0.f);
        r.w = fmaxf(acc[o4 * 4 + 3], 0.f);
        outp[o4] = r;
    }
}

// ---------------------------------------------------------------------------
// Launch: zero -> scatter -> gemm+bias+relu (stream-ordered, graph-capturable)
// Inputs (metadata order): h [N,64] f32, src [E] i32, dst [E] i32,
//                          W [64,64] f32, b [64] f32.  Output: [N,64] f32.
// ---------------------------------------------------------------------------
extern "C" void kernel_launch(void* const* d_in, const int* in_sizes, int n_in,
                              void* d_out, int out_size) {
    const float* h   = (const float*)d_in[0];
    const int*   src = (const int*)d_in[1];
    const int*   dst = (const int*)d_in[2];
    const float* W   = (const float*)d_in[3];
    const float* b   = (const float*)d_in[4];
    float*       out = (float*)d_out;

    (void)in_sizes; (void)n_in; (void)out_size;

    {
        const unsigned n4 = N_NODES * (FEATS / 4);
        zero_kernel<<<(n4 + 255) / 256, 256>>>();
    }
    {
        const unsigned nthreads = N_EDGES * 16u;   // 20M
        scatter_kernel<<<(nthreads + 255) / 256, 256>>>(
            (const float4*)h, src, dst);
    }
    {
        gemm_relu_kernel<<<(N_NODES + 255) / 256, 256>>>(W, b, out);
    }
}

// round 4
// speedup vs baseline: 1.9211x; 1.9211x over previous
#include <cuda_runtime.h>
#include <cstdint>

#define N_NODES 100000
#define N_EDGES 1250000
#define FEATS   64
#define SCAN_BLK 1024
#define N_SCAN_BLKS ((N_NODES + SCAN_BLK - 1) / SCAN_BLK)   // 98

// ---------------------------------------------------------------------------
// Device-global scratch (no allocations allowed).
// ---------------------------------------------------------------------------
__device__ int    g_count[N_NODES];        // per-node in-degree
__device__ int    g_row[N_NODES + 1];      // CSR row offsets (by dst)
__device__ int    g_cursor[N_NODES];       // bucket-fill cursors
__device__ int    g_esrc[N_EDGES];         // src ids grouped by dst
__device__ int    g_bsum[128];             // per-block scan sums
__device__ float4 g_ah4[N_NODES * (FEATS / 4)];  // segment_sum result

// ---------------------------------------------------------------------------
// K1: zero the degree histogram
// ---------------------------------------------------------------------------
__global__ void zero_count_kernel() {
    unsigned i = blockIdx.x * blockDim.x + threadIdx.x;
    if (i < N_NODES) g_count[i] = 0;
}

// ---------------------------------------------------------------------------
// K2: histogram of dst (int REDG.ADD, cheap)
// ---------------------------------------------------------------------------
__global__ __launch_bounds__(256)
void hist_kernel(const int* __restrict__ dst) {
    unsigned e = blockIdx.x * blockDim.x + threadIdx.x;
    if (e < N_EDGES) atomicAdd(&g_count[dst[e]], 1);
}

// ---------------------------------------------------------------------------
// K3: per-block exclusive scan of counts (1024/block), emit block sums
// ---------------------------------------------------------------------------
__global__ __launch_bounds__(SCAN_BLK)
void scan1_kernel() {
    __shared__ int s[SCAN_BLK];
    unsigned gid = blockIdx.x * SCAN_BLK + threadIdx.x;
    int v = (gid < N_NODES) ? g_count[gid] : 0;
    s[threadIdx.x] = v;
    __syncthreads();
    #pragma unroll
    for (int off = 1; off < SCAN_BLK; off <<= 1) {
        int t = (threadIdx.x >= (unsigned)off) ? s[threadIdx.x - off] : 0;
        __syncthreads();
        s[threadIdx.x] += t;
        __syncthreads();
    }
    if (gid < N_NODES) g_row[gid] = s[threadIdx.x] - v;   // exclusive in-block
    if (threadIdx.x == SCAN_BLK - 1) g_bsum[blockIdx.x] = s[SCAN_BLK - 1];
}

// ---------------------------------------------------------------------------
// K4: scan the 98 block sums (single block)
// ---------------------------------------------------------------------------
__global__ __launch_bounds__(128)
void scan2_kernel() {
    __shared__ int s[128];
    int v = (threadIdx.x < N_SCAN_BLKS) ? g_bsum[threadIdx.x] : 0;
    s[threadIdx.x] = v;
    __syncthreads();
    #pragma unroll
    for (int off = 1; off < 128; off <<= 1) {
        int t = (threadIdx.x >= (unsigned)off) ? s[threadIdx.x - off] : 0;
        __syncthreads();
        s[threadIdx.x] += t;
        __syncthreads();
    }
    if (threadIdx.x < N_SCAN_BLKS) g_bsum[threadIdx.x] = s[threadIdx.x] - v;
}

// ---------------------------------------------------------------------------
// K5: add block offsets -> final row starts; init cursors; set row[N]=E
// ---------------------------------------------------------------------------
__global__ __launch_bounds__(256)
void scan3_kernel() {
    unsigned gid = blockIdx.x * blockDim.x + threadIdx.x;
    if (gid < N_NODES) {
        int r = g_row[gid] + g_bsum[gid / SCAN_BLK];
        g_row[gid] = r;
        g_cursor[gid] = r;
    }
    if (gid == 0) g_row[N_NODES] = N_EDGES;
}

// ---------------------------------------------------------------------------
// K6: bucket fill — group src ids by dst
// ---------------------------------------------------------------------------
__global__ __launch_bounds__(256)
void fill_kernel(const int* __restrict__ src, const int* __restrict__ dst) {
    unsigned e = blockIdx.x * blockDim.x + threadIdx.x;
    if (e < N_EDGES) {
        int pos = atomicAdd(&g_cursor[dst[e]], 1);
        g_esrc[pos] = src[e];
    }
}

// ---------------------------------------------------------------------------
// K7: gather-reduce.  16 lanes per node; each lane owns one float4 chunk.
// Zero atomics; h (25.6 MB) is L2-resident -> L2-BW bound.
// Writes every node (deg 0 -> zeros), so no separate zero pass for g_ah4.
// ---------------------------------------------------------------------------
__global__ __launch_bounds__(256)
void gather_kernel(const float4* __restrict__ h4) {
    unsigned t = blockIdx.x * blockDim.x + threadIdx.x;   // < N*16 = 1.6M
    unsigned node = t >> 4;
    unsigned lane = t & 15;
    if (node >= N_NODES) return;

    int beg = __ldg(&g_row[node]);
    int end = __ldg(&g_row[node + 1]);

    float4 acc = make_float4(0.f, 0.f, 0.f, 0.f);
    for (int i = beg; i < end; i++) {
        int s = __ldg(&g_esrc[i]);                 // broadcast within group
        float4 v = __ldg(&h4[(unsigned)s * 16u + lane]);
        acc.x += v.x; acc.y += v.y; acc.z += v.z; acc.w += v.w;
    }
    g_ah4[node * 16u + lane] = acc;
}

// ---------------------------------------------------------------------------
// K8: out = relu(ah @ W^T + b).  W transposed into smem (conflict-free
// float4 broadcast), one thread per node, 64 register accumulators.
// ---------------------------------------------------------------------------
__global__ __launch_bounds__(256)
void gemm_relu_kernel(const float* __restrict__ W,
                      const float* __restrict__ b,
                      float* __restrict__ out) {
    __shared__ float Ws[FEATS * FEATS];   // Ws[k*64 + o] = W[o][k]
    __shared__ float bs[FEATS];

    for (int i = threadIdx.x; i < FEATS * FEATS; i += 256) {
        int o = i >> 6;
        int k = i & 63;
        Ws[k * FEATS + o] = W[i];
    }
    if (threadIdx.x < FEATS) bs[threadIdx.x] = b[threadIdx.x];
    __syncthreads();

    unsigned node = blockIdx.x * 256u + threadIdx.x;
    if (node >= N_NODES) return;

    const float4* arow = &g_ah4[node * 16u];

    float acc[FEATS];
    #pragma unroll
    for (int o = 0; o < FEATS; o++) acc[o] = bs[o];

    #pragma unroll 1
    for (int k4 = 0; k4 < 16; k4++) {
        float4 a = arow[k4];
        float av[4] = {a.x, a.y, a.z, a.w};
        #pragma unroll
        for (int j = 0; j < 4; j++) {
            const float4* wrow =
                reinterpret_cast<const float4*>(Ws + (k4 * 4 + j) * FEATS);
            float aj = av[j];
            #pragma unroll
            for (int o4 = 0; o4 < 16; o4++) {
                float4 w = wrow[o4];
                acc[o4 * 4 + 0] += aj * w.x;
                acc[o4 * 4 + 1] += aj * w.y;
                acc[o4 * 4 + 2] += aj * w.z;
                acc[o4 * 4 + 3] += aj * w.w;
            }
        }
    }

    float4* outp = reinterpret_cast<float4*>(out + node * 64u);
    #pragma unroll
    for (int o4 = 0; o4 < 16; o4++) {
        float4 r;
        r.x = fmaxf(acc[o4 * 4 + 0], 0.f);
        r.y = fmaxf(acc[o4 * 4 + 1], 0.f);
        r.z = fmaxf(acc[o4 * 4 + 2], 0.f);
        r.w = fmaxf(acc[o4 * 4 + 3], 0.f);
        outp[o4] = r;
    }
}

// ---------------------------------------------------------------------------
// Launch pipeline (stream-ordered, graph-capturable):
// zero_count -> hist -> scan1 -> scan2 -> scan3 -> fill -> gather -> gemm
// Inputs: h [N,64] f32, src [E] i32, dst [E] i32, W [64,64] f32, b [64] f32.
// ---------------------------------------------------------------------------
extern "C" void kernel_launch(void* const* d_in, const int* in_sizes, int n_in,
                              void* d_out, int out_size) {
    const float* h   = (const float*)d_in[0];
    const int*   src = (const int*)d_in[1];
    const int*   dst = (const int*)d_in[2];
    const float* W   = (const float*)d_in[3];
    const float* b   = (const float*)d_in[4];
    float*       out = (float*)d_out;

    (void)in_sizes; (void)n_in; (void)out_size;

    zero_count_kernel<<<(N_NODES + 255) / 256, 256>>>();
    hist_kernel<<<(N_EDGES + 255) / 256, 256>>>(dst);
    scan1_kernel<<<N_SCAN_BLKS, SCAN_BLK>>>();
    scan2_kernel<<<1, 128>>>();
    scan3_kernel<<<(N_NODES + 255) / 256, 256>>>();
    fill_kernel<<<(N_EDGES + 255) / 256, 256>>>(src, dst);
    gather_kernel<<<(N_NODES * 16 + 255) / 256, 256>>>((const float4*)h);
    gemm_relu_kernel<<<(N_NODES + 255) / 256, 256>>>(W, b, out);
}